// round 1
// baseline (speedup 1.0000x reference)
#include <cuda_runtime.h>
#include <mma.h>
#include <math.h>
#include <stdint.h>

using namespace nvcuda;

// Problem constants
#define BB 4
#define SS 2048
#define EE 1024
#define HH 16
#define DD 64
#define MTOT (BB*SS)   // 8192
#define SCALING 0.125f // 64^-0.5

// Scratch (allocation-free rule: __device__ globals)
__device__ float g_q[BB*HH*SS*DD];    // [B,H,S,D]
__device__ float g_k[BB*HH*SS*DD];
__device__ float g_v[BB*HH*SS*DD];
__device__ float g_att[BB*SS*EE];     // [B,S,E]

// ---------------------------------------------------------------------------
// Projection GEMM: C[M,N] = A[M,K] @ W[N,K]^T + bias, 3xTF32 (near-fp32 accuracy)
// Block tile 128x128, BK=32, 256 threads = 8 warps (2x4 of 64x32 warp tiles)
// mode 0: write out as [B,H,S,D] with scale; mode 1: row-major [M,N]
// ---------------------------------------------------------------------------
#define PLDS 36
#define PLDC 132
#define PROJ_SMEM ((128*PLDC)*4)   // 67584 B (>= 2*128*PLDS*4 = 36864)

__global__ __launch_bounds__(256, 1)
void proj_kernel(const float* __restrict__ A, const float* __restrict__ W,
                 const float* __restrict__ bias, float* __restrict__ out,
                 float scale, int mode)
{
    extern __shared__ float sm[];
    float* As = sm;               // [128][PLDS]
    float* Ws = sm + 128 * PLDS;  // [128][PLDS]
    float* Cs = sm;               // [128][PLDC] epilogue staging (aliases tiles)

    const int m0 = blockIdx.y * 128;
    const int n0 = blockIdx.x * 128;
    const int tid = threadIdx.x;
    const int wid = tid >> 5;
    const int wm = wid >> 2;   // 0..1
    const int wn = wid & 3;    // 0..3

    wmma::fragment<wmma::accumulator, 16, 16, 8, float> acc[4][2];
#pragma unroll
    for (int i = 0; i < 4; i++)
#pragma unroll
        for (int j = 0; j < 2; j++) wmma::fill_fragment(acc[i][j], 0.0f);

    for (int k0 = 0; k0 < EE; k0 += 32) {
        // Load A tile [128][32] and W tile [128][32] as float4
        {
            int r = tid >> 3;            // 0..31
            int c4 = (tid & 7) * 4;      // 0..28
#pragma unroll
            for (int p = 0; p < 4; p++) {
                int row = r + p * 32;
                *(float4*)&As[row * PLDS + c4] =
                    *(const float4*)&A[(size_t)(m0 + row) * EE + k0 + c4];
                *(float4*)&Ws[row * PLDS + c4] =
                    *(const float4*)&W[(size_t)(n0 + row) * EE + k0 + c4];
            }
        }
        __syncthreads();

#pragma unroll
        for (int kk = 0; kk < 32; kk += 8) {
            wmma::fragment<wmma::matrix_b, 16, 16, 8, wmma::precision::tf32, wmma::col_major> bhi[2], blo[2];
#pragma unroll
            for (int j = 0; j < 2; j++) {
                wmma::fragment<wmma::matrix_b, 16, 16, 8, wmma::precision::tf32, wmma::col_major> braw;
                wmma::load_matrix_sync(braw, &Ws[(wn * 32 + j * 16) * PLDS + kk], PLDS);
#pragma unroll
                for (int e = 0; e < braw.num_elements; e++) {
                    float x = braw.x[e];
                    float hi = wmma::__float_to_tf32(x);
                    bhi[j].x[e] = hi;
                    blo[j].x[e] = wmma::__float_to_tf32(x - hi);
                }
            }
#pragma unroll
            for (int i = 0; i < 4; i++) {
                wmma::fragment<wmma::matrix_a, 16, 16, 8, wmma::precision::tf32, wmma::row_major> araw, ahi, alo;
                wmma::load_matrix_sync(araw, &As[(wm * 64 + i * 16) * PLDS + kk], PLDS);
#pragma unroll
                for (int e = 0; e < araw.num_elements; e++) {
                    float x = araw.x[e];
                    float hi = wmma::__float_to_tf32(x);
                    ahi.x[e] = hi;
                    alo.x[e] = wmma::__float_to_tf32(x - hi);
                }
#pragma unroll
                for (int j = 0; j < 2; j++) {
                    wmma::mma_sync(acc[i][j], ahi, bhi[j], acc[i][j]);
                    wmma::mma_sync(acc[i][j], ahi, blo[j], acc[i][j]);
                    wmma::mma_sync(acc[i][j], alo, bhi[j], acc[i][j]);
                }
            }
        }
        __syncthreads();
    }

    // Epilogue: stage in smem, add bias, scale, scatter per mode
#pragma unroll
    for (int i = 0; i < 4; i++)
#pragma unroll
        for (int j = 0; j < 2; j++)
            wmma::store_matrix_sync(&Cs[(wm * 64 + i * 16) * PLDC + wn * 32 + j * 16],
                                    acc[i][j], PLDC, wmma::mem_row_major);
    __syncthreads();

    {
        int c4 = (tid & 31) * 4;
        for (int rp = 0; rp < 16; rp++) {
            int row = (tid >> 5) + rp * 8;
            int m = m0 + row;
#pragma unroll
            for (int q = 0; q < 4; q++) {
                int n = n0 + c4 + q;
                float v = (Cs[row * PLDC + c4 + q] + bias[n]) * scale;
                if (mode == 0) {
                    int b = m >> 11, s = m & 2047;
                    int h = n >> 6, d = n & 63;
                    out[(((size_t)(b * HH + h)) * SS + s) * DD + d] = v;
                } else {
                    out[(size_t)m * EE + n] = v;
                }
            }
        }
    }
}

// ---------------------------------------------------------------------------
// Flash attention: per block = (b,h) x one 128-row Q tile. 256 threads, 8 warps.
// Scores via tf32 wmma (Q pre-scaled), online softmax with row state in smem,
// PV via tf32 wmma staged through smem (avoids opaque-fragment row rescale).
// ---------------------------------------------------------------------------
#define ALD 68
#define ALDP 132
#define ATTN_SMEM ((128*ALD*4 + 128*ALDP + 3*128)*4)  // 208384 B

__global__ __launch_bounds__(256, 1)
void attn_kernel(const float* __restrict__ Q, const float* __restrict__ K,
                 const float* __restrict__ V, float* __restrict__ out)
{
    extern __shared__ float sm[];
    float* Qs = sm;                 // [128][ALD]
    float* Ks = Qs + 128 * ALD;     // [128][ALD], aliased as PV stage
    float* Vs = Ks + 128 * ALD;     // [128][ALD]
    float* Ps = Vs + 128 * ALD;     // [128][ALDP] scores/probs
    float* Os = Ps + 128 * ALDP;    // [128][ALD] output accumulator
    float* mS = Os + 128 * ALD;     // [128]
    float* lS = mS + 128;
    float* aS = lS + 128;

    const int tid = threadIdx.x;
    const int wid = tid >> 5;
    const int wm = wid >> 2;  // 0..1
    const int wn = wid & 3;   // 0..3
    const int q0 = blockIdx.x * 128;
    const int bh = blockIdx.y;                 // b*H + h
    const size_t base = (size_t)bh * SS * DD;

    // Load Q tile, zero O, init row state
    for (int p = 0; p < 8; p++) {
        int row = (tid >> 4) + p * 16;
        int c4 = (tid & 15) * 4;
        *(float4*)&Qs[row * ALD + c4] = *(const float4*)&Q[base + (size_t)(q0 + row) * DD + c4];
        *(float4*)&Os[row * ALD + c4] = make_float4(0.f, 0.f, 0.f, 0.f);
    }
    if (tid < 128) { mS[tid] = -1e30f; lS[tid] = 0.f; }
    __syncthreads();

    for (int kt = 0; kt < SS / 128; kt++) {
        const int t0 = kt * 128;
        for (int p = 0; p < 8; p++) {
            int row = (tid >> 4) + p * 16;
            int c4 = (tid & 15) * 4;
            *(float4*)&Ks[row * ALD + c4] = *(const float4*)&K[base + (size_t)(t0 + row) * DD + c4];
            *(float4*)&Vs[row * ALD + c4] = *(const float4*)&V[base + (size_t)(t0 + row) * DD + c4];
        }
        __syncthreads();

        // ---- scores: S[128,128] = Qs @ Ks^T (tf32). Warp tile 64x32 (4x2 frags)
        {
            wmma::fragment<wmma::accumulator, 16, 16, 8, float> sacc[4][2];
#pragma unroll
            for (int i = 0; i < 4; i++)
#pragma unroll
                for (int j = 0; j < 2; j++) wmma::fill_fragment(sacc[i][j], 0.0f);

#pragma unroll
            for (int kk = 0; kk < DD; kk += 8) {
                wmma::fragment<wmma::matrix_b, 16, 16, 8, wmma::precision::tf32, wmma::col_major> bf[2];
#pragma unroll
                for (int j = 0; j < 2; j++) {
                    wmma::load_matrix_sync(bf[j], &Ks[(wn * 32 + j * 16) * ALD + kk], ALD);
#pragma unroll
                    for (int e = 0; e < bf[j].num_elements; e++)
                        bf[j].x[e] = wmma::__float_to_tf32(bf[j].x[e]);
                }
#pragma unroll
                for (int i = 0; i < 4; i++) {
                    wmma::fragment<wmma::matrix_a, 16, 16, 8, wmma::precision::tf32, wmma::row_major> af;
                    wmma::load_matrix_sync(af, &Qs[(wm * 64 + i * 16) * ALD + kk], ALD);
#pragma unroll
                    for (int e = 0; e < af.num_elements; e++)
                        af.x[e] = wmma::__float_to_tf32(af.x[e]);
#pragma unroll
                    for (int j = 0; j < 2; j++)
                        wmma::mma_sync(sacc[i][j], af, bf[j], sacc[i][j]);
                }
            }
#pragma unroll
            for (int i = 0; i < 4; i++)
#pragma unroll
                for (int j = 0; j < 2; j++)
                    wmma::store_matrix_sync(&Ps[(wm * 64 + i * 16) * ALDP + wn * 32 + j * 16],
                                            sacc[i][j], ALDP, wmma::mem_row_major);
        }
        __syncthreads();

        // ---- online softmax: 2 threads per row (adjacent lanes), 64 cols each
        {
            int r = tid >> 1, half = tid & 1;
            float* row = &Ps[r * ALDP + half * 64];
            float mo = mS[r];
            float mx = -1e30f;
#pragma unroll 8
            for (int c = 0; c < 64; c++) mx = fmaxf(mx, row[c]);
            mx = fmaxf(mx, __shfl_xor_sync(0xffffffffu, mx, 1));
            float mn = fmaxf(mo, mx);
            float sum = 0.f;
#pragma unroll 8
            for (int c = 0; c < 64; c++) {
                float pv = __expf(row[c] - mn);
                row[c] = pv;
                sum += pv;
            }
            sum += __shfl_xor_sync(0xffffffffu, sum, 1);
            float alpha = __expf(mo - mn);
            if (half == 0) {
                mS[r] = mn;
                lS[r] = lS[r] * alpha + sum;
                aS[r] = alpha;
            }
        }
        __syncthreads();

        // ---- PV: stage[128,64] = P @ Vs (tf32). Warp tile 64x16 (4x1 frags)
        {
            wmma::fragment<wmma::accumulator, 16, 16, 8, float> pacc[4];
#pragma unroll
            for (int i = 0; i < 4; i++) wmma::fill_fragment(pacc[i], 0.0f);

#pragma unroll
            for (int t = 0; t < 128; t += 8) {
                wmma::fragment<wmma::matrix_b, 16, 16, 8, wmma::precision::tf32, wmma::row_major> bf;
                wmma::load_matrix_sync(bf, &Vs[t * ALD + wn * 16], ALD);
#pragma unroll
                for (int e = 0; e < bf.num_elements; e++)
                    bf.x[e] = wmma::__float_to_tf32(bf.x[e]);
#pragma unroll
                for (int i = 0; i < 4; i++) {
                    wmma::fragment<wmma::matrix_a, 16, 16, 8, wmma::precision::tf32, wmma::row_major> af;
                    wmma::load_matrix_sync(af, &Ps[(wm * 64 + i * 16) * ALDP + t], ALDP);
#pragma unroll
                    for (int e = 0; e < af.num_elements; e++)
                        af.x[e] = wmma::__float_to_tf32(af.x[e]);
                    wmma::mma_sync(pacc[i], af, bf, pacc[i]);
                }
            }
            // Stage through Ks (K tile fully consumed by scores phase)
#pragma unroll
            for (int i = 0; i < 4; i++)
                wmma::store_matrix_sync(&Ks[(wm * 64 + i * 16) * ALD + wn * 16],
                                        pacc[i], ALD, wmma::mem_row_major);
        }
        __syncthreads();

        // ---- O = O * alpha(row) + stage
        for (int p = 0; p < 8; p++) {
            int row = (tid >> 4) + p * 16;
            int c4 = (tid & 15) * 4;
            float a = aS[row];
            float4 o = *(float4*)&Os[row * ALD + c4];
            float4 st = *(float4*)&Ks[row * ALD + c4];
            o.x = o.x * a + st.x;
            o.y = o.y * a + st.y;
            o.z = o.z * a + st.z;
            o.w = o.w * a + st.w;
            *(float4*)&Os[row * ALD + c4] = o;
        }
        __syncthreads();
    }

    // Final: O /= l, write to attn buffer [B,S,E] at column h*64
    {
        int b = bh >> 4, h = bh & 15;
        for (int p = 0; p < 8; p++) {
            int row = (tid >> 4) + p * 16;
            int c4 = (tid & 15) * 4;
            float inv = 1.0f / lS[row];
            float4 v = *(float4*)&Os[row * ALD + c4];
            size_t o = ((size_t)b * SS + (q0 + row)) * EE + h * DD + c4;
            float4 w = make_float4(v.x * inv, v.y * inv, v.z * inv, v.w * inv);
            *(float4*)&out[o] = w;
        }
    }
}

// ---------------------------------------------------------------------------
extern "C" void kernel_launch(void* const* d_in, const int* in_sizes, int n_in,
                              void* d_out, int out_size)
{
    const float* query = (const float*)d_in[0];
    const float* key   = (const float*)d_in[1];
    const float* value = (const float*)d_in[2];
    const float* q_w   = (const float*)d_in[3];
    const float* q_b   = (const float*)d_in[4];
    const float* k_w   = (const float*)d_in[5];
    const float* k_b   = (const float*)d_in[6];
    const float* v_w   = (const float*)d_in[7];
    const float* v_b   = (const float*)d_in[8];
    const float* out_w = (const float*)d_in[9];
    const float* out_b = (const float*)d_in[10];
    float* out = (float*)d_out;

    float *gq, *gk, *gv, *gatt;
    cudaGetSymbolAddress((void**)&gq, g_q);
    cudaGetSymbolAddress((void**)&gk, g_k);
    cudaGetSymbolAddress((void**)&gv, g_v);
    cudaGetSymbolAddress((void**)&gatt, g_att);

    cudaFuncSetAttribute(proj_kernel, cudaFuncAttributeMaxDynamicSharedMemorySize, PROJ_SMEM);
    cudaFuncSetAttribute(attn_kernel, cudaFuncAttributeMaxDynamicSharedMemorySize, ATTN_SMEM);

    dim3 pgrid(EE / 128, MTOT / 128);  // (8, 64)
    proj_kernel<<<pgrid, 256, PROJ_SMEM>>>(query, q_w, q_b, gq, SCALING, 0);
    proj_kernel<<<pgrid, 256, PROJ_SMEM>>>(key,   k_w, k_b, gk, 1.0f,    0);
    proj_kernel<<<pgrid, 256, PROJ_SMEM>>>(value, v_w, v_b, gv, 1.0f,    0);

    dim3 agrid(SS / 128, BB * HH);     // (16, 64)
    attn_kernel<<<agrid, 256, ATTN_SMEM>>>(gq, gk, gv, gatt);

    proj_kernel<<<pgrid, 256, PROJ_SMEM>>>(gatt, out_w, out_b, out, 1.0f, 1);
}

// round 2
// speedup vs baseline: 2.7797x; 2.7797x over previous
#include <cuda_runtime.h>
#include <cuda_bf16.h>
#include <mma.h>
#include <stdint.h>

using namespace nvcuda;

// Problem constants
#define BB 4
#define SS 2048
#define EE 1024
#define HH 16
#define DD 64
#define MTOT (BB*SS)   // 8192
#define SCALING 0.125f

// Scratch (allocation-free rule: __device__ globals)
__device__ float g_q[BB*HH*SS*DD];    // [B,H,S,D]
__device__ float g_k[BB*HH*SS*DD];
__device__ float g_v[BB*HH*SS*DD];
__device__ float g_att[BB*SS*EE];     // [B,S,E]

__device__ __forceinline__ float to_tf32(float x) {
    uint32_t u; asm("cvt.rna.tf32.f32 %0, %1;" : "=r"(u) : "f"(x));
    return __uint_as_float(u);
}

__device__ __forceinline__ void mma_tf32(float* c,
    uint32_t a0, uint32_t a1, uint32_t a2, uint32_t a3,
    uint32_t b0, uint32_t b1)
{
    asm volatile("mma.sync.aligned.m16n8k8.row.col.f32.tf32.tf32.f32 "
        "{%0,%1,%2,%3},{%4,%5,%6,%7},{%8,%9},{%0,%1,%2,%3};\n"
        : "+f"(c[0]), "+f"(c[1]), "+f"(c[2]), "+f"(c[3])
        : "r"(a0), "r"(a1), "r"(a2), "r"(a3), "r"(b0), "r"(b1));
}

// within-8 column permutation: puts k-cols c and c+4 adjacent (fragment float2 loads)
__device__ __forceinline__ int perm8(int c) { return 2 * (c & 3) + ((c >> 2) & 1); }

// ---------------------------------------------------------------------------
// Projection GEMM: C[M,N] = A[M,K] @ W[N,K]^T + bias. bf16 split-3 (hi/lo).
// Split done ONCE at smem store. Block 128x128, BK=32, 256 thr = 8 warps (2x4).
// ---------------------------------------------------------------------------
#define PK 32
#define PLB 40      // bf16 row pitch
#define PLDC 132
#define PROJ_SMEM (128*PLDC*4)   // 67584 B; bf16 tiles use first 40960 B

__global__ __launch_bounds__(256, 2)
void proj_kernel(const float* __restrict__ A, const float* __restrict__ W,
                 const float* __restrict__ bias, float* __restrict__ out,
                 float scale, int mode)
{
    extern __shared__ char smraw[];
    __nv_bfloat16* Ahi = (__nv_bfloat16*)smraw;
    __nv_bfloat16* Alo = Ahi + 128 * PLB;
    __nv_bfloat16* Whi = Alo + 128 * PLB;
    __nv_bfloat16* Wlo = Whi + 128 * PLB;
    float* Cs = (float*)smraw;   // epilogue staging aliases the tiles

    const int m0 = blockIdx.y * 128;
    const int n0 = blockIdx.x * 128;
    const int tid = threadIdx.x;
    const int wid = tid >> 5;
    const int wm = wid >> 2;   // 0..1
    const int wn = wid & 3;    // 0..3

    wmma::fragment<wmma::accumulator, 16, 16, 16, float> acc[4][2];
#pragma unroll
    for (int i = 0; i < 4; i++)
#pragma unroll
        for (int j = 0; j < 2; j++) wmma::fill_fragment(acc[i][j], 0.0f);

    const int r = tid >> 3;          // 0..31
    const int c4 = (tid & 7) * 4;    // 0..28

    for (int k0 = 0; k0 < EE; k0 += PK) {
#pragma unroll
        for (int p = 0; p < 4; p++) {
            int row = r + p * 32;
            float4 av = *(const float4*)&A[(size_t)(m0 + row) * EE + k0 + c4];
            float4 wv = *(const float4*)&W[(size_t)(n0 + row) * EE + k0 + c4];
            int o = row * PLB + c4;
            float aa[4] = {av.x, av.y, av.z, av.w};
            float ww[4] = {wv.x, wv.y, wv.z, wv.w};
#pragma unroll
            for (int e = 0; e < 4; e++) {
                __nv_bfloat16 h = __float2bfloat16_rn(aa[e]);
                Ahi[o + e] = h;
                Alo[o + e] = __float2bfloat16_rn(aa[e] - __bfloat162float(h));
                __nv_bfloat16 g = __float2bfloat16_rn(ww[e]);
                Whi[o + e] = g;
                Wlo[o + e] = __float2bfloat16_rn(ww[e] - __bfloat162float(g));
            }
        }
        __syncthreads();

#pragma unroll
        for (int kk = 0; kk < PK; kk += 16) {
            wmma::fragment<wmma::matrix_b, 16, 16, 16, __nv_bfloat16, wmma::col_major> bhi[2], blo[2];
#pragma unroll
            for (int j = 0; j < 2; j++) {
                wmma::load_matrix_sync(bhi[j], &Whi[(wn * 32 + j * 16) * PLB + kk], PLB);
                wmma::load_matrix_sync(blo[j], &Wlo[(wn * 32 + j * 16) * PLB + kk], PLB);
            }
#pragma unroll
            for (int i = 0; i < 4; i++) {
                wmma::fragment<wmma::matrix_a, 16, 16, 16, __nv_bfloat16, wmma::row_major> ahi, alo;
                wmma::load_matrix_sync(ahi, &Ahi[(wm * 64 + i * 16) * PLB + kk], PLB);
                wmma::load_matrix_sync(alo, &Alo[(wm * 64 + i * 16) * PLB + kk], PLB);
#pragma unroll
                for (int j = 0; j < 2; j++) {
                    wmma::mma_sync(acc[i][j], ahi, bhi[j], acc[i][j]);
                    wmma::mma_sync(acc[i][j], ahi, blo[j], acc[i][j]);
                    wmma::mma_sync(acc[i][j], alo, bhi[j], acc[i][j]);
                }
            }
        }
        __syncthreads();
    }

    // Epilogue: stage in smem, add bias, scale, scatter per mode
#pragma unroll
    for (int i = 0; i < 4; i++)
#pragma unroll
        for (int j = 0; j < 2; j++)
            wmma::store_matrix_sync(&Cs[(wm * 64 + i * 16) * PLDC + wn * 32 + j * 16],
                                    acc[i][j], PLDC, wmma::mem_row_major);
    __syncthreads();

    {
        int cc = (tid & 31) * 4;
        for (int rp = 0; rp < 16; rp++) {
            int row = (tid >> 5) + rp * 8;
            int m = m0 + row;
#pragma unroll
            for (int q = 0; q < 4; q++) {
                int n = n0 + cc + q;
                float v = (Cs[row * PLDC + cc + q] + bias[n]) * scale;
                if (mode == 0) {
                    int b = m >> 11, s = m & 2047;
                    int h = n >> 6, d = n & 63;
                    out[(((size_t)(b * HH + h)) * SS + s) * DD + d] = v;
                } else {
                    out[(size_t)m * EE + n] = v;
                }
            }
        }
    }
}

// ---------------------------------------------------------------------------
// Flash attention: raw mma.sync m16n8k8 tf32. Block = (b,h) x 128 Q rows.
// 8 warps; each warp owns 16 Q rows. KT=64 key tile. Softmax + O fully in regs.
// smem tiles hold pre-converted tf32 with permuted k-columns -> float2 frags.
// ---------------------------------------------------------------------------
#define KT 64
#define LDK 72
#define NKT (SS/KT)   // 32
#define ATTN_SMEM ((128*LDK + 64*LDK + 64*LDK + 8*16*LDK)*4)  // 110592 B

__global__ __launch_bounds__(256, 2)
void attn_kernel(const float* __restrict__ Q, const float* __restrict__ K,
                 const float* __restrict__ V, float* __restrict__ out)
{
    extern __shared__ float sm[];
    float* Qs = sm;                  // [128][LDK] tf32, cols permuted, pre-scaled
    float* Ks = Qs + 128 * LDK;      // [64][LDK]  tf32, cols (d) permuted
    float* Vt = Ks + 64 * LDK;       // [64][LDK]  V transposed: [d][kt], kt permuted
    float* Ps = Vt + 64 * LDK;       // 8 x [16][LDK] per-warp P, kt cols permuted

    const int tid = threadIdx.x;
    const int w = tid >> 5;
    const int l = tid & 31;
    const int qa = l >> 2;           // 0..7
    const int cq = l & 3;            // 0..3
    const int q0 = blockIdx.x * 128;
    const int bh = blockIdx.y;       // b*H + h
    const size_t base = (size_t)bh * SS * DD;
    float* Pw = Ps + w * 16 * LDK;
    const int pc0 = perm8(2 * cq);       // P store col offsets within n8 group
    const int pc1 = perm8(2 * cq + 1);

    // Load Q tile: scale, tf32, permute cols
    {
        int row = tid >> 1;
        int cb = (tid & 1) * 32;
        const float* src = &Q[base + (size_t)(q0 + row) * DD + cb];
        float* dst = &Qs[row * LDK];
#pragma unroll
        for (int c = 0; c < 32; c += 4) {
            float4 v = *(const float4*)&src[c];
            float vv[4] = {v.x, v.y, v.z, v.w};
#pragma unroll
            for (int e = 0; e < 4; e++) {
                int col = cb + c + e;
                dst[(col & ~7) + perm8(col & 7)] = to_tf32(vv[e] * SCALING);
            }
        }
    }

    float m_[2] = {-1e30f, -1e30f};
    float l_[2] = {0.f, 0.f};
    float o_[8][4];
#pragma unroll
    for (int dg = 0; dg < 8; dg++)
#pragma unroll
        for (int e = 0; e < 4; e++) o_[dg][e] = 0.f;

    for (int kt = 0; kt < NKT; kt++) {
        __syncthreads();   // protect Ks/Vt reuse (also orders Qs on iter 0)
        {
            int row = tid >> 2;
            int cb = (tid & 3) * 16;
            int t0 = kt * KT;
            const float* ksrc = &K[base + (size_t)(t0 + row) * DD + cb];
            const float* vsrc = &V[base + (size_t)(t0 + row) * DD + cb];
            int prow = (row & ~7) + perm8(row & 7);
#pragma unroll
            for (int c = 0; c < 16; c += 4) {
                float4 kv = *(const float4*)&ksrc[c];
                float4 vv = *(const float4*)&vsrc[c];
                float ka[4] = {kv.x, kv.y, kv.z, kv.w};
                float va[4] = {vv.x, vv.y, vv.z, vv.w};
#pragma unroll
                for (int e = 0; e < 4; e++) {
                    int col = cb + c + e;
                    Ks[row * LDK + (col & ~7) + perm8(col & 7)] = to_tf32(ka[e]);
                    Vt[col * LDK + prow] = to_tf32(va[e]);
                }
            }
        }
        __syncthreads();

        // ---- scores: per-warp 16x64 in registers
        float s[8][4];
#pragma unroll
        for (int ng = 0; ng < 8; ng++) {
            s[ng][0] = 0.f; s[ng][1] = 0.f; s[ng][2] = 0.f; s[ng][3] = 0.f;
        }
#pragma unroll
        for (int kk = 0; kk < 8; kk++) {
            float2 aA = *(float2*)&Qs[(w * 16 + qa) * LDK + kk * 8 + 2 * cq];
            float2 aB = *(float2*)&Qs[(w * 16 + qa + 8) * LDK + kk * 8 + 2 * cq];
            uint32_t a0 = __float_as_uint(aA.x), a2 = __float_as_uint(aA.y);
            uint32_t a1 = __float_as_uint(aB.x), a3 = __float_as_uint(aB.y);
#pragma unroll
            for (int ng = 0; ng < 8; ng++) {
                float2 bv = *(float2*)&Ks[(ng * 8 + qa) * LDK + kk * 8 + 2 * cq];
                mma_tf32(s[ng], a0, a1, a2, a3,
                         __float_as_uint(bv.x), __float_as_uint(bv.y));
            }
        }

        // ---- online softmax in registers (rows qa, qa+8 of this warp)
        float mxa = -1e30f, mxb = -1e30f;
#pragma unroll
        for (int ng = 0; ng < 8; ng++) {
            mxa = fmaxf(mxa, fmaxf(s[ng][0], s[ng][1]));
            mxb = fmaxf(mxb, fmaxf(s[ng][2], s[ng][3]));
        }
        mxa = fmaxf(mxa, __shfl_xor_sync(0xffffffffu, mxa, 1));
        mxa = fmaxf(mxa, __shfl_xor_sync(0xffffffffu, mxa, 2));
        mxb = fmaxf(mxb, __shfl_xor_sync(0xffffffffu, mxb, 1));
        mxb = fmaxf(mxb, __shfl_xor_sync(0xffffffffu, mxb, 2));
        float mna = fmaxf(m_[0], mxa), mnb = fmaxf(m_[1], mxb);
        float suma = 0.f, sumb = 0.f;
#pragma unroll
        for (int ng = 0; ng < 8; ng++) {
            float p0 = to_tf32(__expf(s[ng][0] - mna));
            float p1 = to_tf32(__expf(s[ng][1] - mna));
            float p2 = to_tf32(__expf(s[ng][2] - mnb));
            float p3 = to_tf32(__expf(s[ng][3] - mnb));
            suma += p0 + p1;
            sumb += p2 + p3;
            Pw[qa * LDK + ng * 8 + pc0] = p0;
            Pw[qa * LDK + ng * 8 + pc1] = p1;
            Pw[(qa + 8) * LDK + ng * 8 + pc0] = p2;
            Pw[(qa + 8) * LDK + ng * 8 + pc1] = p3;
        }
        suma += __shfl_xor_sync(0xffffffffu, suma, 1);
        suma += __shfl_xor_sync(0xffffffffu, suma, 2);
        sumb += __shfl_xor_sync(0xffffffffu, sumb, 1);
        sumb += __shfl_xor_sync(0xffffffffu, sumb, 2);
        float ala = __expf(m_[0] - mna), alb = __expf(m_[1] - mnb);
        m_[0] = mna; m_[1] = mnb;
        l_[0] = l_[0] * ala + suma;
        l_[1] = l_[1] * alb + sumb;
#pragma unroll
        for (int dg = 0; dg < 8; dg++) {
            o_[dg][0] *= ala; o_[dg][1] *= ala;
            o_[dg][2] *= alb; o_[dg][3] *= alb;
        }
        __syncwarp();

        // ---- PV: O(16x64) += P(16x64) @ V(64x64)
#pragma unroll
        for (int kk = 0; kk < 8; kk++) {
            float2 aA = *(float2*)&Pw[qa * LDK + kk * 8 + 2 * cq];
            float2 aB = *(float2*)&Pw[(qa + 8) * LDK + kk * 8 + 2 * cq];
            uint32_t a0 = __float_as_uint(aA.x), a2 = __float_as_uint(aA.y);
            uint32_t a1 = __float_as_uint(aB.x), a3 = __float_as_uint(aB.y);
#pragma unroll
            for (int dg = 0; dg < 8; dg++) {
                float2 bv = *(float2*)&Vt[(dg * 8 + qa) * LDK + kk * 8 + 2 * cq];
                mma_tf32(o_[dg], a0, a1, a2, a3,
                         __float_as_uint(bv.x), __float_as_uint(bv.y));
            }
        }
        __syncwarp();
    }

    // Final: O /= l, write [B,S,E] at column h*64
    {
        int b = bh >> 4, h = bh & 15;
        float inva = 1.0f / l_[0], invb = 1.0f / l_[1];
        int rowa = q0 + w * 16 + qa;
        int rowb = rowa + 8;
#pragma unroll
        for (int dg = 0; dg < 8; dg++) {
            int col = h * 64 + dg * 8 + 2 * cq;
            float2 va = make_float2(o_[dg][0] * inva, o_[dg][1] * inva);
            float2 vb = make_float2(o_[dg][2] * invb, o_[dg][3] * invb);
            *(float2*)&out[((size_t)b * SS + rowa) * EE + col] = va;
            *(float2*)&out[((size_t)b * SS + rowb) * EE + col] = vb;
        }
    }
}

// ---------------------------------------------------------------------------
extern "C" void kernel_launch(void* const* d_in, const int* in_sizes, int n_in,
                              void* d_out, int out_size)
{
    const float* query = (const float*)d_in[0];
    const float* key   = (const float*)d_in[1];
    const float* value = (const float*)d_in[2];
    const float* q_w   = (const float*)d_in[3];
    const float* q_b   = (const float*)d_in[4];
    const float* k_w   = (const float*)d_in[5];
    const float* k_b   = (const float*)d_in[6];
    const float* v_w   = (const float*)d_in[7];
    const float* v_b   = (const float*)d_in[8];
    const float* out_w = (const float*)d_in[9];
    const float* out_b = (const float*)d_in[10];
    float* out = (float*)d_out;

    float *gq, *gk, *gv, *gatt;
    cudaGetSymbolAddress((void**)&gq, g_q);
    cudaGetSymbolAddress((void**)&gk, g_k);
    cudaGetSymbolAddress((void**)&gv, g_v);
    cudaGetSymbolAddress((void**)&gatt, g_att);

    cudaFuncSetAttribute(proj_kernel, cudaFuncAttributeMaxDynamicSharedMemorySize, PROJ_SMEM);
    cudaFuncSetAttribute(attn_kernel, cudaFuncAttributeMaxDynamicSharedMemorySize, ATTN_SMEM);

    dim3 pgrid(EE / 128, MTOT / 128);  // (8, 64)
    proj_kernel<<<pgrid, 256, PROJ_SMEM>>>(query, q_w, q_b, gq, 1.0f, 0);
    proj_kernel<<<pgrid, 256, PROJ_SMEM>>>(key,   k_w, k_b, gk, 1.0f, 0);
    proj_kernel<<<pgrid, 256, PROJ_SMEM>>>(value, v_w, v_b, gv, 1.0f, 0);

    dim3 agrid(SS / 128, BB * HH);     // (16, 64)
    attn_kernel<<<agrid, 256, ATTN_SMEM>>>(gq, gk, gv, gatt);

    proj_kernel<<<pgrid, 256, PROJ_SMEM>>>(gatt, out_w, out_b, out, 1.0f, 1);
}